// round 5
// baseline (speedup 1.0000x reference)
#include <cuda_runtime.h>
#include <cstdint>
#include <cstddef>

// ---------------------------------------------------------------------------
// Monarch-like two-stage block-diagonal interconnect with softmax-gated
// connectivity.
//   conn1 = softmax(c1*3, axis=i)   c1: [128][64][64]  ([n][i][m])
//   conn2 = softmax(c2*3, axis=n)   c2: [64][128][128] ([m][n][o])
//   t[b,n,m]   = sum_i x[b, n*64+i]   * conn1[n,i,m]
//   out[b,m,o] = sum_n t[b,n,m]       * conn2[m,n,o]
// t is materialized in TRANSPOSED layout t2[b][m][n] so stage-2 reads are
// fully coalesced. Compute uses tf32 mma.sync (m16n8k8) with fp32 accum.
// ---------------------------------------------------------------------------

#define HID     8192
#define NB1     128     // stage-1 blocks (n)
#define I1      64      // inputs per stage-1 block (i)
#define M1      64      // outputs per stage-1 block (m)
#define NB2     64      // stage-2 blocks (m)
#define I2      128     // inputs per stage-2 block (n)
#define O2      128     // outputs per stage-2 block (o)
#define MAXB    4096

// Device scratch (allowed: __device__ globals, no cudaMalloc)
__device__ float g_conn1[NB1 * I1 * M1];      // [n][i][m]
__device__ float g_conn2[NB2 * I2 * O2];      // [m][n][o]
__device__ float g_t[(size_t)MAXB * HID];     // t2: [b][m][n]

// ---------------------------------------------------------------------------
// helpers
// ---------------------------------------------------------------------------
__device__ __forceinline__ unsigned f2tf(float f) {
    unsigned u;
    asm("cvt.rna.tf32.f32 %0, %1;" : "=r"(u) : "f"(f));
    return u;
}

__device__ __forceinline__ void mma_tf32(float* d,
                                         unsigned a0, unsigned a1,
                                         unsigned a2, unsigned a3,
                                         unsigned b0, unsigned b1) {
    asm volatile(
        "mma.sync.aligned.m16n8k8.row.col.f32.tf32.tf32.f32 "
        "{%0,%1,%2,%3}, {%4,%5,%6,%7}, {%8,%9}, {%0,%1,%2,%3};\n"
        : "+f"(d[0]), "+f"(d[1]), "+f"(d[2]), "+f"(d[3])
        : "r"(a0), "r"(a1), "r"(a2), "r"(a3), "r"(b0), "r"(b1));
}

// ---------------------------------------------------------------------------
// Softmax precompute kernels. Thread <-> one (block, out) pair; the reduced
// axis is strided but consecutive threads cover the contiguous fast axis, so
// every gmem access in the i/n loop is warp-coalesced.
// ---------------------------------------------------------------------------
__global__ void softmax1_kernel(const float* __restrict__ c1) {
    int idx = blockIdx.x * blockDim.x + threadIdx.x;   // 128*64 = 8192
    int n = idx >> 6, m = idx & 63;
    const float* p = c1 + (size_t)n * (I1 * M1) + m;
    float mx = -1e30f;
    for (int i = 0; i < I1; i++) mx = fmaxf(mx, p[i * M1] * 3.0f);
    float s = 0.0f;
    for (int i = 0; i < I1; i++) s += expf(p[i * M1] * 3.0f - mx);
    float inv = 1.0f / s;
    float* q = g_conn1 + (size_t)n * (I1 * M1) + m;
    for (int i = 0; i < I1; i++) q[i * M1] = expf(p[i * M1] * 3.0f - mx) * inv;
}

__global__ void softmax2_kernel(const float* __restrict__ c2) {
    int idx = blockIdx.x * blockDim.x + threadIdx.x;   // 64*128 = 8192
    int m = idx >> 7, o = idx & 127;
    const float* p = c2 + (size_t)m * (I2 * O2) + o;
    float mx = -1e30f;
    for (int i = 0; i < I2; i++) mx = fmaxf(mx, p[i * O2] * 3.0f);
    float s = 0.0f;
    for (int i = 0; i < I2; i++) s += expf(p[i * O2] * 3.0f - mx);
    float inv = 1.0f / s;
    float* q = g_conn2 + (size_t)m * (I2 * O2) + o;
    for (int i = 0; i < I2; i++) q[i * O2] = expf(p[i * O2] * 3.0f - mx) * inv;
}

// ---------------------------------------------------------------------------
// Stage 1: CTA = (btile of 32 rows, group of 8 n-blocks). Computes
// t2[b][m][n] for its 32b x 64m x 8n region. Output staged in smem so gmem
// writes are 32B-aligned contiguous chunks (sector-perfect).
// smem: xs [32][520] (tf32 bits), cs [64][72], ts [32][64][9]  -> 158720 B
// ---------------------------------------------------------------------------
#define S1_BT   32
#define XS_STR  520   // 520 % 32 == 8 -> conflict-free fragment loads
#define CS_STR  72    // 72  % 32 == 8
#define TS_STR  9
#define SMEM1   ((S1_BT * XS_STR + I1 * CS_STR + S1_BT * M1 * TS_STR) * 4)

__global__ void __launch_bounds__(256, 1)
stage1_kernel(const float* __restrict__ x) {
    extern __shared__ unsigned char smem_raw[];
    unsigned* xsu = (unsigned*)smem_raw;                 // [32][520]
    unsigned* csu = xsu + S1_BT * XS_STR;                // [64][72]
    float*    ts  = (float*)(csu + I1 * CS_STR);         // [32][64][9]

    const int tid = threadIdx.x;
    const int bt  = blockIdx.x;
    const int nh  = blockIdx.y;            // n_hi: 0..15
    const int b0  = bt * S1_BT;

    // Load x slab [32 x 512] (cols nh*512 .. +511), convert to tf32 bits.
    {
        const float4* x4 = (const float4*)x;
        size_t rowbase = ((size_t)b0 * HID + (size_t)nh * 512) >> 2;
        for (int i = tid; i < S1_BT * 128; i += 256) {
            int b = i >> 7, c4 = i & 127;
            float4 v = x4[rowbase + (size_t)b * (HID / 4) + c4];
            int o = b * XS_STR + c4 * 4;
            xsu[o + 0] = f2tf(v.x);
            xsu[o + 1] = f2tf(v.y);
            xsu[o + 2] = f2tf(v.z);
            xsu[o + 3] = f2tf(v.w);
        }
    }

    const int w    = tid >> 5;
    const int lane = tid & 31;
    const int g    = lane >> 2;   // groupID
    const int tg   = lane & 3;    // thread-in-group
    const int brow = w >> 2;      // 0..1 -> rows 16*brow
    const int mcol = w & 3;       // 0..3 -> m base 16*mcol

    for (int nl = 0; nl < 8; nl++) {
        const int n = nh * 8 + nl;
        __syncthreads();   // prev iter's cs reads done / xs slab ready
        // load conn1[n] -> cs[i][m] (tf32 bits)
        for (int i = tid; i < I1 * M1; i += 256) {
            int ii = i >> 6, mm = i & 63;
            csu[ii * CS_STR + mm] = f2tf(g_conn1[((size_t)n * I1 + ii) * M1 + mm]);
        }
        __syncthreads();

        float acc[2][4] = {};
        #pragma unroll
        for (int ks = 0; ks < 8; ks++) {
            const int xc = nl * 64 + ks * 8 + tg;
            const int r  = brow * 16 + g;
            unsigned a0 = xsu[r * XS_STR + xc];
            unsigned a1 = xsu[(r + 8) * XS_STR + xc];
            unsigned a2 = xsu[r * XS_STR + xc + 4];
            unsigned a3 = xsu[(r + 8) * XS_STR + xc + 4];
            const int ck = ks * 8 + tg;
            #pragma unroll
            for (int j = 0; j < 2; j++) {
                int mm = mcol * 16 + j * 8 + g;
                unsigned bb0 = csu[ck * CS_STR + mm];
                unsigned bb1 = csu[(ck + 4) * CS_STR + mm];
                mma_tf32(acc[j], a0, a1, a2, a3, bb0, bb1);
            }
        }
        // stage results to smem: ts[b][m][nl]
        const int r = brow * 16 + g;
        #pragma unroll
        for (int j = 0; j < 2; j++) {
            int mm = mcol * 16 + j * 8 + 2 * tg;
            ts[(r * 64 + mm) * TS_STR + nl]           = acc[j][0];
            ts[(r * 64 + mm + 1) * TS_STR + nl]       = acc[j][1];
            ts[((r + 8) * 64 + mm) * TS_STR + nl]     = acc[j][2];
            ts[((r + 8) * 64 + mm + 1) * TS_STR + nl] = acc[j][3];
        }
    }
    __syncthreads();

    // Write ts -> t2[b][m][nh*8 .. +7] as two float4 per (b,m) chunk.
    for (int c = tid; c < S1_BT * M1; c += 256) {
        int b = c >> 6, m = c & 63;
        float v[8];
        #pragma unroll
        for (int e = 0; e < 8; e++) v[e] = ts[(b * 64 + m) * TS_STR + e];
        float4* dst = (float4*)(g_t + (size_t)(b0 + b) * HID + m * 128 + nh * 8);
        dst[0] = make_float4(v[0], v[1], v[2], v[3]);
        dst[1] = make_float4(v[4], v[5], v[6], v[7]);
    }
}

// ---------------------------------------------------------------------------
// Stage 2: CTA = (btile of 128 rows, one m-block). GEMM [128b x 128o, K=128n]
// A = t2[btile][m][:]  (coalesced contiguous 512B rows)
// B = conn2[m]         ([n][o])
// smem: As [128][136] + Bs [128][136] (tf32 bits) -> 139264 B (conflict-free)
// ---------------------------------------------------------------------------
#define S2_BT   128
#define AS_STR  136   // 136 % 32 == 8 -> conflict-free fragment loads
#define SMEM2   (2 * S2_BT * AS_STR * 4)

__global__ void __launch_bounds__(256, 1)
stage2_kernel(float* __restrict__ out) {
    extern __shared__ unsigned char smem_raw[];
    unsigned* As = (unsigned*)smem_raw;          // [128][136]
    unsigned* Bs = As + S2_BT * AS_STR;          // [128][136]

    const int tid = threadIdx.x;
    const int bt  = blockIdx.x;
    const int m   = blockIdx.y;
    const int b0  = bt * S2_BT;

    {
        const float4* t4 = (const float4*)g_t;
        size_t abase = ((size_t)b0 * HID + (size_t)m * 128) >> 2;
        for (int i = tid; i < S2_BT * 32; i += 256) {
            int b = i >> 5, c4 = i & 31;
            float4 v = t4[abase + (size_t)b * (HID / 4) + c4];
            int o = b * AS_STR + c4 * 4;
            As[o + 0] = f2tf(v.x);
            As[o + 1] = f2tf(v.y);
            As[o + 2] = f2tf(v.z);
            As[o + 3] = f2tf(v.w);
        }
        const float4* c4p = (const float4*)g_conn2;
        size_t bbase = ((size_t)m * I2 * O2) >> 2;
        for (int i = tid; i < I2 * 32; i += 256) {
            int n = i >> 5, c4 = i & 31;
            float4 v = c4p[bbase + (size_t)n * (O2 / 4) + c4];
            int o = n * AS_STR + c4 * 4;
            Bs[o + 0] = f2tf(v.x);
            Bs[o + 1] = f2tf(v.y);
            Bs[o + 2] = f2tf(v.z);
            Bs[o + 3] = f2tf(v.w);
        }
    }
    __syncthreads();

    const int w    = tid >> 5;
    const int lane = tid & 31;
    const int g    = lane >> 2;
    const int tg   = lane & 3;
    const int brow = w & 3;      // rows base 32*brow
    const int ocol = w >> 2;     // o base 64*ocol

    float acc[2][8][4] = {};
    #pragma unroll
    for (int ks = 0; ks < 16; ks++) {
        const int k0 = ks * 8;
        unsigned a[2][4];
        #pragma unroll
        for (int rt = 0; rt < 2; rt++) {
            int r = brow * 32 + rt * 16 + g;
            a[rt][0] = As[r * AS_STR + k0 + tg];
            a[rt][1] = As[(r + 8) * AS_STR + k0 + tg];
            a[rt][2] = As[r * AS_STR + k0 + 4 + tg];
            a[rt][3] = As[(r + 8) * AS_STR + k0 + 4 + tg];
        }
        #pragma unroll
        for (int ct = 0; ct < 8; ct++) {
            int o = ocol * 64 + ct * 8 + g;
            unsigned bb0 = Bs[(k0 + tg) * AS_STR + o];
            unsigned bb1 = Bs[(k0 + 4 + tg) * AS_STR + o];
            #pragma unroll
            for (int rt = 0; rt < 2; rt++)
                mma_tf32(acc[rt][ct], a[rt][0], a[rt][1], a[rt][2], a[rt][3],
                         bb0, bb1);
        }
    }

    // epilogue: out[b][m*128 + o]
    #pragma unroll
    for (int rt = 0; rt < 2; rt++) {
        int r = brow * 32 + rt * 16 + g;
        #pragma unroll
        for (int ct = 0; ct < 8; ct++) {
            int o = ocol * 64 + ct * 8 + 2 * tg;
            float2* p0 = (float2*)(out + (size_t)(b0 + r) * HID + m * 128 + o);
            *p0 = make_float2(acc[rt][ct][0], acc[rt][ct][1]);
            float2* p1 = (float2*)(out + (size_t)(b0 + r + 8) * HID + m * 128 + o);
            *p1 = make_float2(acc[rt][ct][2], acc[rt][ct][3]);
        }
    }
}

// ---------------------------------------------------------------------------
// launch
// ---------------------------------------------------------------------------
extern "C" void kernel_launch(void* const* d_in, const int* in_sizes, int n_in,
                              void* d_out, int out_size) {
    const float* x  = (const float*)d_in[0];
    const float* c1 = (const float*)d_in[1];
    const float* c2 = (const float*)d_in[2];
    float* out = (float*)d_out;
    const int B = in_sizes[0] / HID;   // 4096

    cudaFuncSetAttribute(stage1_kernel,
                         cudaFuncAttributeMaxDynamicSharedMemorySize, SMEM1);
    cudaFuncSetAttribute(stage2_kernel,
                         cudaFuncAttributeMaxDynamicSharedMemorySize, SMEM2);

    softmax1_kernel<<<(NB1 * M1) / 256, 256>>>(c1);
    softmax2_kernel<<<(NB2 * O2) / 256, 256>>>(c2);
    stage1_kernel<<<dim3(B / S1_BT, NB1 / 8), 256, SMEM1>>>(x);
    stage2_kernel<<<dim3(B / S2_BT, NB2), 256, SMEM2>>>(out);
}

// round 6
// speedup vs baseline: 2.3795x; 2.3795x over previous
#include <cuda_runtime.h>
#include <cstdint>
#include <cstddef>

// ---------------------------------------------------------------------------
// Monarch-like two-stage block-diagonal interconnect, softmax-gated.
//   conn1 = softmax(c1*3, axis=i)   c1: [128][64][64]  ([n][i][m])
//   conn2 = softmax(c2*3, axis=n)   c2: [64][128][128] ([m][n][o])
//   t[b,n,m]   = sum_i x[b, n*64+i] * conn1[n,i,m]
//   out[b,m,o] = sum_n t[b,n,m]     * conn2[m,n,o]
// t materialized transposed: t2[b][m][n] (coalesced stage-2 reads).
// All weights + t pre-rounded to tf32 -> consumers cp.async raw bits to MMA.
// ---------------------------------------------------------------------------

#define HID     8192
#define NB1     128
#define I1      64
#define M1      64
#define NB2     64
#define I2      128
#define O2      128
#define MAXB    4096

__device__ float g_conn1[NB1 * I1 * M1];      // [n][i][m]  (tf32-rounded)
__device__ float g_conn2[NB2 * I2 * O2];      // [m][n][o]  (tf32-rounded)
__device__ float g_t[(size_t)MAXB * HID];     // t2: [b][m][n] (tf32-rounded)

// ---------------------------------------------------------------------------
// helpers
// ---------------------------------------------------------------------------
__device__ __forceinline__ unsigned f2tf(float f) {
    unsigned u;
    asm("cvt.rna.tf32.f32 %0, %1;" : "=r"(u) : "f"(f));
    return u;
}

__device__ __forceinline__ void mma_tf32(float* d,
                                         unsigned a0, unsigned a1,
                                         unsigned a2, unsigned a3,
                                         unsigned b0, unsigned b1) {
    asm volatile(
        "mma.sync.aligned.m16n8k8.row.col.f32.tf32.tf32.f32 "
        "{%0,%1,%2,%3}, {%4,%5,%6,%7}, {%8,%9}, {%0,%1,%2,%3};\n"
        : "+f"(d[0]), "+f"(d[1]), "+f"(d[2]), "+f"(d[3])
        : "r"(a0), "r"(a1), "r"(a2), "r"(a3), "r"(b0), "r"(b1));
}

__device__ __forceinline__ void cp16(unsigned smem_addr, const void* gptr) {
    asm volatile("cp.async.cg.shared.global [%0], [%1], 16;"
                 :: "r"(smem_addr), "l"(gptr));
}
__device__ __forceinline__ void cp_commit() {
    asm volatile("cp.async.commit_group;");
}
template <int N> __device__ __forceinline__ void cp_wait() {
    asm volatile("cp.async.wait_group %0;" :: "n"(N));
}

// ---------------------------------------------------------------------------
// Softmax precompute (outputs tf32-rounded so consumers skip conversion).
// ---------------------------------------------------------------------------
__global__ void softmax1_kernel(const float* __restrict__ c1) {
    int idx = blockIdx.x * blockDim.x + threadIdx.x;   // 8192
    int n = idx >> 6, m = idx & 63;
    const float* p = c1 + (size_t)n * (I1 * M1) + m;
    float mx = -1e30f;
    for (int i = 0; i < I1; i++) mx = fmaxf(mx, p[i * M1] * 3.0f);
    float s = 0.0f;
    for (int i = 0; i < I1; i++) s += expf(p[i * M1] * 3.0f - mx);
    float inv = 1.0f / s;
    float* q = g_conn1 + (size_t)n * (I1 * M1) + m;
    for (int i = 0; i < I1; i++)
        q[i * M1] = __uint_as_float(f2tf(expf(p[i * M1] * 3.0f - mx) * inv));
}

__global__ void softmax2_kernel(const float* __restrict__ c2) {
    int idx = blockIdx.x * blockDim.x + threadIdx.x;   // 8192
    int m = idx >> 7, o = idx & 127;
    const float* p = c2 + (size_t)m * (I2 * O2) + o;
    float mx = -1e30f;
    for (int i = 0; i < I2; i++) mx = fmaxf(mx, p[i * O2] * 3.0f);
    float s = 0.0f;
    for (int i = 0; i < I2; i++) s += expf(p[i * O2] * 3.0f - mx);
    float inv = 1.0f / s;
    float* q = g_conn2 + (size_t)m * (I2 * O2) + o;
    for (int i = 0; i < I2; i++)
        q[i * O2] = __uint_as_float(f2tf(expf(p[i * O2] * 3.0f - mx) * inv));
}

// ---------------------------------------------------------------------------
// Stage 1: CTA = (64-row btile, group of 8 n-blocks). 512 threads, 16 warps.
// x streamed per-n-chunk via cp.async (pipelined, depth 2); conn1 double-
// buffered. Accumulators for all 8 n held in registers (64/thread); epilogue
// writes t2[b][m][8n] as two float4 (32B sector-perfect), tf32-rounded.
// smem: xs raw fp32 [64][520] + cs tf32 [2][64][72]  -> 169,984 B
// ---------------------------------------------------------------------------
#define S1_BT   64
#define XS_STR  520
#define CS_STR  72
#define SMEM1   ((S1_BT * XS_STR + 2 * I1 * CS_STR) * 4)

__global__ void __launch_bounds__(512, 1)
stage1_kernel(const float* __restrict__ x) {
    extern __shared__ unsigned char smem_raw[];
    float*    xs = (float*)smem_raw;                    // [64][520]
    unsigned* cs = (unsigned*)(xs + S1_BT * XS_STR);    // [2][64][72]

    const int tid = threadIdx.x;
    const int bt  = blockIdx.x;
    const int nh  = blockIdx.y;            // 0..15
    const int b0  = bt * S1_BT;

    const unsigned xs_base = (unsigned)__cvta_generic_to_shared(xs);
    const unsigned cs_base = (unsigned)__cvta_generic_to_shared(cs);

    auto issue_x = [&](int nl) {
        // 64 rows x 64 floats (256B/row) -> 1024 x 16B chunks
        for (int c = tid; c < S1_BT * 16; c += 512) {
            int row = c >> 4, c4 = c & 15;
            const float* src = x + (size_t)(b0 + row) * HID
                                 + (size_t)nh * 512 + nl * 64 + c4 * 4;
            cp16(xs_base + (unsigned)(row * XS_STR + nl * 64 + c4 * 4) * 4, src);
        }
    };
    auto issue_c = [&](int nl) {
        int n = nh * 8 + nl, slot = nl & 1;
        for (int c = tid; c < I1 * 16; c += 512) {
            int i = c >> 4, c4 = c & 15;
            const float* src = g_conn1 + (size_t)n * (I1 * M1) + i * M1 + c4 * 4;
            cp16(cs_base + (unsigned)(slot * I1 * CS_STR + i * CS_STR + c4 * 4) * 4,
                 src);
        }
    };

    issue_x(0); issue_c(0); cp_commit();
    issue_x(1); issue_c(1); cp_commit();

    const int w    = tid >> 5;
    const int lane = tid & 31;
    const int g    = lane >> 2;
    const int tg   = lane & 3;
    const int brow = w >> 2;   // 0..3 -> rows 16*brow
    const int mcol = w & 3;    // 0..3 -> m base 16*mcol

    float acc[8][2][4] = {};

    #pragma unroll
    for (int nl = 0; nl < 8; nl++) {
        if (nl < 7) cp_wait<1>(); else cp_wait<0>();
        __syncthreads();
        const unsigned* csl = cs + (nl & 1) * I1 * CS_STR;
        #pragma unroll
        for (int ks = 0; ks < 8; ks++) {
            const int xc = nl * 64 + ks * 8 + tg;
            const int r  = brow * 16 + g;
            unsigned a0 = f2tf(xs[r * XS_STR + xc]);
            unsigned a1 = f2tf(xs[(r + 8) * XS_STR + xc]);
            unsigned a2 = f2tf(xs[r * XS_STR + xc + 4]);
            unsigned a3 = f2tf(xs[(r + 8) * XS_STR + xc + 4]);
            const int ck = ks * 8 + tg;
            #pragma unroll
            for (int j = 0; j < 2; j++) {
                int mm = mcol * 16 + j * 8 + g;
                mma_tf32(acc[nl][j], a0, a1, a2, a3,
                         csl[ck * CS_STR + mm], csl[(ck + 4) * CS_STR + mm]);
            }
        }
        __syncthreads();
        if (nl + 2 < 8) { issue_x(nl + 2); issue_c(nl + 2); cp_commit(); }
    }

    // Epilogue: t2[b0+row][mm][nh*8 .. +7], tf32-rounded, 2x float4 per chunk.
    const int rbase = brow * 16 + g;
    #pragma unroll
    for (int j = 0; j < 2; j++) {
        #pragma unroll
        for (int rs = 0; rs < 2; rs++) {
            #pragma unroll
            for (int ms = 0; ms < 2; ms++) {
                const int row = rbase + rs * 8;
                const int mm  = mcol * 16 + j * 8 + 2 * tg + ms;
                const int e   = rs * 2 + ms;
                float4 v0, v1;
                v0.x = __uint_as_float(f2tf(acc[0][j][e]));
                v0.y = __uint_as_float(f2tf(acc[1][j][e]));
                v0.z = __uint_as_float(f2tf(acc[2][j][e]));
                v0.w = __uint_as_float(f2tf(acc[3][j][e]));
                v1.x = __uint_as_float(f2tf(acc[4][j][e]));
                v1.y = __uint_as_float(f2tf(acc[5][j][e]));
                v1.z = __uint_as_float(f2tf(acc[6][j][e]));
                v1.w = __uint_as_float(f2tf(acc[7][j][e]));
                float4* dst = (float4*)(g_t + (size_t)(b0 + row) * HID
                                            + mm * 128 + nh * 8);
                dst[0] = v0;
                dst[1] = v1;
            }
        }
    }
}

// ---------------------------------------------------------------------------
// Stage 2: CTA = (m-block, btile-group). 512 threads. Bs (conn2[m]) loaded
// once; A tiles (128 rows of t2, already tf32) double-buffered via cp.async.
// smem: Ab [2][128][136] + Bs [128][136] -> 208,896 B
// ---------------------------------------------------------------------------
#define AS_STR  136
#define NG2     8
#define SMEM2   (3 * 128 * AS_STR * 4)

__global__ void __launch_bounds__(512, 1)
stage2_kernel(float* __restrict__ out, int B) {
    extern __shared__ unsigned char smem_raw[];
    unsigned* Ab = (unsigned*)smem_raw;           // [2][128][136]
    unsigned* Bs = Ab + 2 * 128 * AS_STR;         // [128][136]

    const int tid = threadIdx.x;
    const int m   = blockIdx.y;
    const int nb  = B / 128 / NG2;                // 4

    const unsigned ab_base = (unsigned)__cvta_generic_to_shared(Ab);
    const unsigned bs_base = (unsigned)__cvta_generic_to_shared(Bs);

    auto issue_A = [&](int k) {
        const int b0   = (blockIdx.x * nb + k) * 128;
        const int slot = k & 1;
        for (int c = tid; c < 128 * 32; c += 512) {
            int row = c >> 5, c4 = c & 31;
            cp16(ab_base + (unsigned)(slot * 128 * AS_STR + row * AS_STR + c4 * 4) * 4,
                 g_t + (size_t)(b0 + row) * HID + m * 128 + c4 * 4);
        }
    };

    // Bs + A(0) in group 1
    for (int c = tid; c < 128 * 32; c += 512) {
        int row = c >> 5, c4 = c & 31;
        cp16(bs_base + (unsigned)(row * AS_STR + c4 * 4) * 4,
             g_conn2 + (size_t)m * (I2 * O2) + row * O2 + c4 * 4);
    }
    issue_A(0); cp_commit();

    const int w    = tid >> 5;
    const int lane = tid & 31;
    const int g    = lane >> 2;
    const int tg   = lane & 3;
    const int brow = w & 3;    // rows base 32*brow
    const int ocol = w >> 2;   // o base 32*ocol

    for (int k = 0; k < nb; k++) {
        if (k + 1 < nb) { issue_A(k + 1); cp_commit(); cp_wait<1>(); }
        else            { cp_wait<0>(); }
        __syncthreads();

        const unsigned* As = Ab + (k & 1) * 128 * AS_STR;
        float acc[2][4][4] = {};
        #pragma unroll
        for (int ks = 0; ks < 16; ks++) {
            const int k0 = ks * 8;
            unsigned a[2][4];
            #pragma unroll
            for (int rt = 0; rt < 2; rt++) {
                int r = brow * 32 + rt * 16 + g;
                a[rt][0] = As[r * AS_STR + k0 + tg];
                a[rt][1] = As[(r + 8) * AS_STR + k0 + tg];
                a[rt][2] = As[r * AS_STR + k0 + 4 + tg];
                a[rt][3] = As[(r + 8) * AS_STR + k0 + 4 + tg];
            }
            #pragma unroll
            for (int ct = 0; ct < 4; ct++) {
                int o = ocol * 32 + ct * 8 + g;
                unsigned b0v = Bs[(k0 + tg) * AS_STR + o];
                unsigned b1v = Bs[(k0 + 4 + tg) * AS_STR + o];
                #pragma unroll
                for (int rt = 0; rt < 2; rt++)
                    mma_tf32(acc[rt][ct], a[rt][0], a[rt][1], a[rt][2], a[rt][3],
                             b0v, b1v);
            }
        }

        // epilogue
        const int b0 = (blockIdx.x * nb + k) * 128;
        #pragma unroll
        for (int rt = 0; rt < 2; rt++) {
            int r = b0 + brow * 32 + rt * 16 + g;
            #pragma unroll
            for (int ct = 0; ct < 4; ct++) {
                int o = m * 128 + ocol * 32 + ct * 8 + 2 * tg;
                *(float2*)(out + (size_t)r * HID + o) =
                    make_float2(acc[rt][ct][0], acc[rt][ct][1]);
                *(float2*)(out + (size_t)(r + 8) * HID + o) =
                    make_float2(acc[rt][ct][2], acc[rt][ct][3]);
            }
        }
        __syncthreads();
    }
}

// ---------------------------------------------------------------------------
// launch
// ---------------------------------------------------------------------------
extern "C" void kernel_launch(void* const* d_in, const int* in_sizes, int n_in,
                              void* d_out, int out_size) {
    const float* x  = (const float*)d_in[0];
    const float* c1 = (const float*)d_in[1];
    const float* c2 = (const float*)d_in[2];
    float* out = (float*)d_out;
    const int B = in_sizes[0] / HID;   // 4096

    cudaFuncSetAttribute(stage1_kernel,
                         cudaFuncAttributeMaxDynamicSharedMemorySize, SMEM1);
    cudaFuncSetAttribute(stage2_kernel,
                         cudaFuncAttributeMaxDynamicSharedMemorySize, SMEM2);

    softmax1_kernel<<<(NB1 * M1) / 256, 256>>>(c1);
    softmax2_kernel<<<(NB2 * O2) / 256, 256>>>(c2);
    stage1_kernel<<<dim3(B / S1_BT, 16), 512, SMEM1>>>(x);
    stage2_kernel<<<dim3(NG2, NB2), 512, SMEM2>>>(out, B);
}

// round 7
// speedup vs baseline: 2.5248x; 1.0611x over previous
#include <cuda_runtime.h>
#include <cstdint>
#include <cstddef>

// ---------------------------------------------------------------------------
// Monarch-like two-stage block-diagonal interconnect, softmax-gated.
//   conn1 = softmax(c1*3, axis=i)   c1: [128][64][64]  ([n][i][m])
//   conn2 = softmax(c2*3, axis=n)   c2: [64][128][128] ([m][n][o])
//   t[b,n,m]   = sum_i x[b, n*64+i] * conn1[n,i,m]
//   out[b,m,o] = sum_n t[b,n,m]     * conn2[m,n,o]
// t materialized transposed: t2[b][m][n] (coalesced stage-2 reads).
// Weights + t pre-rounded to tf32 -> consumers cp.async raw bits to MMA.
// ---------------------------------------------------------------------------

#define HID     8192
#define NB1     128
#define I1      64
#define M1      64
#define NB2     64
#define I2      128
#define O2      128
#define MAXB    4096

__device__ float g_conn1[NB1 * I1 * M1];      // [n][i][m]  (tf32-rounded)
__device__ float g_conn2[NB2 * I2 * O2];      // [m][n][o]  (tf32-rounded)
__device__ float g_t[(size_t)MAXB * HID];     // t2: [b][m][n] (tf32-rounded)

// ---------------------------------------------------------------------------
// helpers
// ---------------------------------------------------------------------------
__device__ __forceinline__ unsigned f2tf(float f) {
    unsigned u;
    asm("cvt.rna.tf32.f32 %0, %1;" : "=r"(u) : "f"(f));
    return u;
}

__device__ __forceinline__ void mma_tf32(float* d,
                                         unsigned a0, unsigned a1,
                                         unsigned a2, unsigned a3,
                                         unsigned b0, unsigned b1) {
    asm volatile(
        "mma.sync.aligned.m16n8k8.row.col.f32.tf32.tf32.f32 "
        "{%0,%1,%2,%3}, {%4,%5,%6,%7}, {%8,%9}, {%0,%1,%2,%3};\n"
        : "+f"(d[0]), "+f"(d[1]), "+f"(d[2]), "+f"(d[3])
        : "r"(a0), "r"(a1), "r"(a2), "r"(a3), "r"(b0), "r"(b1));
}

__device__ __forceinline__ void cp16(unsigned smem_addr, const void* gptr) {
    asm volatile("cp.async.cg.shared.global [%0], [%1], 16;"
                 :: "r"(smem_addr), "l"(gptr));
}
__device__ __forceinline__ void cp_commit() {
    asm volatile("cp.async.commit_group;");
}
template <int N> __device__ __forceinline__ void cp_wait() {
    asm volatile("cp.async.wait_group %0;" :: "n"(N));
}

// ---------------------------------------------------------------------------
// Merged softmax precompute (outputs tf32-rounded). First 8192 threads do
// conn1, next 8192 do conn2 — both run concurrently in one launch.
// ---------------------------------------------------------------------------
__global__ void softmax_kernel(const float* __restrict__ c1,
                               const float* __restrict__ c2) {
    int gid = blockIdx.x * blockDim.x + threadIdx.x;   // 16384
    if (gid < NB1 * M1) {
        int n = gid >> 6, m = gid & 63;
        const float* p = c1 + (size_t)n * (I1 * M1) + m;
        float mx = -1e30f;
        for (int i = 0; i < I1; i++) mx = fmaxf(mx, p[i * M1] * 3.0f);
        float s = 0.0f;
        for (int i = 0; i < I1; i++) s += expf(p[i * M1] * 3.0f - mx);
        float inv = 1.0f / s;
        float* q = g_conn1 + (size_t)n * (I1 * M1) + m;
        for (int i = 0; i < I1; i++)
            q[i * M1] = __uint_as_float(f2tf(expf(p[i * M1] * 3.0f - mx) * inv));
    } else {
        int idx = gid - NB1 * M1;
        int m = idx >> 7, o = idx & 127;
        const float* p = c2 + (size_t)m * (I2 * O2) + o;
        float mx = -1e30f;
        for (int i = 0; i < I2; i++) mx = fmaxf(mx, p[i * O2] * 3.0f);
        float s = 0.0f;
        for (int i = 0; i < I2; i++) s += expf(p[i * O2] * 3.0f - mx);
        float inv = 1.0f / s;
        float* q = g_conn2 + (size_t)m * (I2 * O2) + o;
        for (int i = 0; i < I2; i++)
            q[i * O2] = __uint_as_float(f2tf(expf(p[i * O2] * 3.0f - mx) * inv));
    }
}

// ---------------------------------------------------------------------------
// Stage 1: CTA = (64-row btile, group of 8 n-blocks). 512 threads, 16 warps.
// Pipeline: group k = (x chunk k, conn1 block k); 4-slot conn ring, issue
// distance 3, ONE barrier per iteration. The slot being filled at iter nl is
// (nl+3)&3 == (nl-1)&3 — consumed in iter nl-1, protected by this iter's
// barrier. Accumulators for all 8 n in registers; epilogue writes t2 as
// tf32-rounded 32B chunks.
// smem: xs raw fp32 [64][520] + cs tf32 [4][64][72]  -> 206,848 B
// ---------------------------------------------------------------------------
#define S1_BT    64
#define XS_STR   520
#define CS_STR   72
#define CS_SLOTS 4
#define SMEM1    ((S1_BT * XS_STR + CS_SLOTS * I1 * CS_STR) * 4)

__global__ void __launch_bounds__(512, 1)
stage1_kernel(const float* __restrict__ x) {
    extern __shared__ unsigned char smem_raw[];
    float*    xs = (float*)smem_raw;                    // [64][520]
    unsigned* cs = (unsigned*)(xs + S1_BT * XS_STR);    // [4][64][72]

    const int tid = threadIdx.x;
    const int bt  = blockIdx.x;
    const int nh  = blockIdx.y;            // 0..15
    const int b0  = bt * S1_BT;

    const unsigned xs_base = (unsigned)__cvta_generic_to_shared(xs);
    const unsigned cs_base = (unsigned)__cvta_generic_to_shared(cs);

    auto issue_group = [&](int k) {
        // x chunk k: 64 rows x 64 floats
        for (int c = tid; c < S1_BT * 16; c += 512) {
            int row = c >> 4, c4 = c & 15;
            const float* src = x + (size_t)(b0 + row) * HID
                                 + (size_t)nh * 512 + k * 64 + c4 * 4;
            cp16(xs_base + (unsigned)(row * XS_STR + k * 64 + c4 * 4) * 4, src);
        }
        // conn1 block (nh*8+k) into ring slot k&3
        int n = nh * 8 + k, slot = k & (CS_SLOTS - 1);
        for (int c = tid; c < I1 * 16; c += 512) {
            int i = c >> 4, c4 = c & 15;
            const float* src = g_conn1 + (size_t)n * (I1 * M1) + i * M1 + c4 * 4;
            cp16(cs_base + (unsigned)(slot * I1 * CS_STR + i * CS_STR + c4 * 4) * 4,
                 src);
        }
        cp_commit();
    };

    issue_group(0);
    issue_group(1);
    issue_group(2);

    const int w    = tid >> 5;
    const int lane = tid & 31;
    const int g    = lane >> 2;
    const int tg   = lane & 3;
    const int brow = w >> 2;   // 0..3 -> rows 16*brow
    const int mcol = w & 3;    // 0..3 -> m base 16*mcol

    float acc[8][2][4] = {};

    #pragma unroll
    for (int nl = 0; nl < 8; nl++) {
        if (nl < 6)       cp_wait<2>();
        else if (nl == 6) cp_wait<1>();
        else              cp_wait<0>();
        __syncthreads();
        if (nl + 3 < 8) issue_group(nl + 3);

        const unsigned* csl = cs + (nl & (CS_SLOTS - 1)) * I1 * CS_STR;
        #pragma unroll
        for (int ks = 0; ks < 8; ks++) {
            const int xc = nl * 64 + ks * 8 + tg;
            const int r  = brow * 16 + g;
            unsigned a0 = f2tf(xs[r * XS_STR + xc]);
            unsigned a1 = f2tf(xs[(r + 8) * XS_STR + xc]);
            unsigned a2 = f2tf(xs[r * XS_STR + xc + 4]);
            unsigned a3 = f2tf(xs[(r + 8) * XS_STR + xc + 4]);
            const int ck = ks * 8 + tg;
            #pragma unroll
            for (int j = 0; j < 2; j++) {
                int mm = mcol * 16 + j * 8 + g;
                mma_tf32(acc[nl][j], a0, a1, a2, a3,
                         csl[ck * CS_STR + mm], csl[(ck + 4) * CS_STR + mm]);
            }
        }
    }

    // Epilogue: t2[b0+row][mm][nh*8 .. +7], tf32-rounded, 2x float4 per chunk.
    const int rbase = brow * 16 + g;
    #pragma unroll
    for (int j = 0; j < 2; j++) {
        #pragma unroll
        for (int rs = 0; rs < 2; rs++) {
            #pragma unroll
            for (int ms = 0; ms < 2; ms++) {
                const int row = rbase + rs * 8;
                const int mm  = mcol * 16 + j * 8 + 2 * tg + ms;
                const int e   = rs * 2 + ms;
                float4 v0, v1;
                v0.x = __uint_as_float(f2tf(acc[0][j][e]));
                v0.y = __uint_as_float(f2tf(acc[1][j][e]));
                v0.z = __uint_as_float(f2tf(acc[2][j][e]));
                v0.w = __uint_as_float(f2tf(acc[3][j][e]));
                v1.x = __uint_as_float(f2tf(acc[4][j][e]));
                v1.y = __uint_as_float(f2tf(acc[5][j][e]));
                v1.z = __uint_as_float(f2tf(acc[6][j][e]));
                v1.w = __uint_as_float(f2tf(acc[7][j][e]));
                float4* dst = (float4*)(g_t + (size_t)(b0 + row) * HID
                                            + mm * 128 + nh * 8);
                dst[0] = v0;
                dst[1] = v1;
            }
        }
    }
}

// ---------------------------------------------------------------------------
// Stage 2: CTA = (m-block, group of 2 btiles). 512 threads. Bs (conn2[m])
// loaded once; BOTH A tiles issued in prologue (full-depth prefetch); two
// barriers per CTA total. grid = 16 x 64 = 1024 CTAs (6.9 waves, ~1% tail).
// smem: Ab [2][128][136] + Bs [128][136] -> 208,896 B
// ---------------------------------------------------------------------------
#define AS_STR  136
#define NG2     16
#define SMEM2   (3 * 128 * AS_STR * 4)

__global__ void __launch_bounds__(512, 1)
stage2_kernel(float* __restrict__ out, int B) {
    extern __shared__ unsigned char smem_raw[];
    unsigned* Ab = (unsigned*)smem_raw;           // [2][128][136]
    unsigned* Bs = Ab + 2 * 128 * AS_STR;         // [128][136]

    const int tid = threadIdx.x;
    const int m   = blockIdx.y;
    const int nb  = B / 128 / NG2;                // 2

    const unsigned ab_base = (unsigned)__cvta_generic_to_shared(Ab);
    const unsigned bs_base = (unsigned)__cvta_generic_to_shared(Bs);

    auto issue_A = [&](int k) {
        const int b0   = (blockIdx.x * nb + k) * 128;
        const int slot = k & 1;
        for (int c = tid; c < 128 * 32; c += 512) {
            int row = c >> 5, c4 = c & 31;
            cp16(ab_base + (unsigned)(slot * 128 * AS_STR + row * AS_STR + c4 * 4) * 4,
                 g_t + (size_t)(b0 + row) * HID + m * 128 + c4 * 4);
        }
        cp_commit();
    };

    // Prologue: Bs + A(0) in group 0, A(1) in group 1.
    for (int c = tid; c < 128 * 32; c += 512) {
        int row = c >> 5, c4 = c & 31;
        cp16(bs_base + (unsigned)(row * AS_STR + c4 * 4) * 4,
             g_conn2 + (size_t)m * (I2 * O2) + row * O2 + c4 * 4);
    }
    issue_A(0);        // commit: group 0 = Bs + A0
    issue_A(1);        // commit: group 1 = A1

    const int w    = tid >> 5;
    const int lane = tid & 31;
    const int g    = lane >> 2;
    const int tg   = lane & 3;
    const int brow = w & 3;    // rows base 32*brow
    const int ocol = w >> 2;   // o base 32*ocol

    #pragma unroll
    for (int k = 0; k < 2; k++) {
        if (k == 0) cp_wait<1>();
        else        cp_wait<0>();
        __syncthreads();

        const unsigned* As = Ab + (k & 1) * 128 * AS_STR;
        float acc[2][4][4] = {};
        #pragma unroll
        for (int ks = 0; ks < 16; ks++) {
            const int k0 = ks * 8;
            unsigned a[2][4];
            #pragma unroll
            for (int rt = 0; rt < 2; rt++) {
                int r = brow * 32 + rt * 16 + g;
                a[rt][0] = As[r * AS_STR + k0 + tg];
                a[rt][1] = As[(r + 8) * AS_STR + k0 + tg];
                a[rt][2] = As[r * AS_STR + k0 + 4 + tg];
                a[rt][3] = As[(r + 8) * AS_STR + k0 + 4 + tg];
            }
            #pragma unroll
            for (int ct = 0; ct < 4; ct++) {
                int o = ocol * 32 + ct * 8 + g;
                unsigned b0v = Bs[(k0 + tg) * AS_STR + o];
                unsigned b1v = Bs[(k0 + 4 + tg) * AS_STR + o];
                #pragma unroll
                for (int rt = 0; rt < 2; rt++)
                    mma_tf32(acc[rt][ct], a[rt][0], a[rt][1], a[rt][2], a[rt][3],
                             b0v, b1v);
            }
        }

        // epilogue
        const int b0 = (blockIdx.x * nb + k) * 128;
        #pragma unroll
        for (int rt = 0; rt < 2; rt++) {
            int r = b0 + brow * 32 + rt * 16 + g;
            #pragma unroll
            for (int ct = 0; ct < 4; ct++) {
                int o = m * 128 + ocol * 32 + ct * 8 + 2 * tg;
                *(float2*)(out + (size_t)r * HID + o) =
                    make_float2(acc[rt][ct][0], acc[rt][ct][1]);
                *(float2*)(out + (size_t)(r + 8) * HID + o) =
                    make_float2(acc[rt][ct][2], acc[rt][ct][3]);
            }
        }
    }
}

// ---------------------------------------------------------------------------
// launch
// ---------------------------------------------------------------------------
extern "C" void kernel_launch(void* const* d_in, const int* in_sizes, int n_in,
                              void* d_out, int out_size) {
    const float* x  = (const float*)d_in[0];
    const float* c1 = (const float*)d_in[1];
    const float* c2 = (const float*)d_in[2];
    float* out = (float*)d_out;
    const int B = in_sizes[0] / HID;   // 4096

    cudaFuncSetAttribute(stage1_kernel,
                         cudaFuncAttributeMaxDynamicSharedMemorySize, SMEM1);
    cudaFuncSetAttribute(stage2_kernel,
                         cudaFuncAttributeMaxDynamicSharedMemorySize, SMEM2);

    softmax_kernel<<<(NB1 * M1 + NB2 * O2) / 256, 256>>>(c1, c2);
    stage1_kernel<<<dim3(B / S1_BT, 16), 512, SMEM1>>>(x);
    stage2_kernel<<<dim3(NG2, NB2), 512, SMEM2>>>(out, B);
}